// round 3
// baseline (speedup 1.0000x reference)
#include <cuda_runtime.h>

#define NROWS 2048
#define DIN 256
#define H 64
#define HP 32   // h pairs

// Hidden activations, n-major: logical float2 at [n*HP + hp].
// Declared as ulonglong2 for guaranteed 16B alignment (vector access).
__device__ ulonglong2 g_agh[NROWS * HP / 2];
__device__ ulonglong2 g_abh[NROWS * HP / 2];

typedef unsigned long long u64;

__device__ __forceinline__ u64 f2add(u64 a, u64 b) {
    u64 d; asm("add.rn.f32x2 %0, %1, %2;" : "=l"(d) : "l"(a), "l"(b)); return d;
}
__device__ __forceinline__ u64 f2fma(u64 a, u64 b, u64 c) {
    u64 d; asm("fma.rn.f32x2 %0, %1, %2, %3;" : "=l"(d) : "l"(a), "l"(b), "l"(c)); return d;
}
__device__ __forceinline__ u64 f2relu(u64 s) {
    float lo, hi;
    asm("mov.b64 {%0, %1}, %2;" : "=f"(lo), "=f"(hi) : "l"(s));
    lo = fmaxf(lo, 0.0f);
    hi = fmaxf(hi, 0.0f);
    u64 d; asm("mov.b64 %0, {%1, %2};" : "=l"(d) : "f"(lo), "f"(hi)); return d;
}

// ---------------------------------------------------------------------------
// Kernel 1 (fused, software-pipelined): hidden for BOTH embeddings.
// blocks [0,128) -> ag (+b1), [128,256) -> ab. 16 rows/block.
// K tiled by 128; tile-1 global loads issued into registers while tile-0
// computes, so only one DRAM latency is exposed.
// Output n-major float2 at [n*HP + hp] (coalesced stores).
// ---------------------------------------------------------------------------
__global__ void __launch_bounds__(256) hidden_kernel(
    const float* __restrict__ ag, const float* __restrict__ ab,
    const float* __restrict__ W1, const float* __restrict__ b1)
{
    __shared__ float  embs[16][128];    //  8 KB
    __shared__ float2 w1s[128][32];     // 32 KB

    const int tid = threadIdx.x;
    const int hp  = tid & 31;
    const int ng  = tid >> 5;           // 0..7
    const int which = blockIdx.x >> 7;  // 0 = ag, 1 = ab
    const int n0  = (blockIdx.x & 127) * 16;
    const int koff = which ? DIN : 0;
    const float* __restrict__ emb = which ? ab : ag;

    // per-thread load indices
    const int er = tid >> 5, ec4 = tid & 31;     // emb: rows er, er+8? no: idx-based below
    (void)er; (void)ec4;

    float acc00, acc01, acc10, acc11;
    if (which == 0) {
        float2 bv = ((const float2*)b1)[hp];
        acc00 = bv.x; acc01 = bv.y; acc10 = bv.x; acc11 = bv.y;
    } else {
        acc00 = acc01 = acc10 = acc11 = 0.0f;
    }

    float4 e_pf[2], w_pf[8];

    // ---- load tile 0 into registers, store to smem ----
    #pragma unroll
    for (int t = 0; t < 2; t++) {
        int idx = tid + t * 256, r = idx >> 5, c4 = idx & 31;
        e_pf[t] = ((const float4*)(emb + (size_t)(n0 + r) * DIN))[c4];
    }
    #pragma unroll
    for (int t = 0; t < 8; t++) {
        int idx = tid + t * 256, kk = idx >> 4, q = idx & 15;
        w_pf[t] = ((const float4*)(W1 + (size_t)(koff + kk) * H))[q];
    }
    #pragma unroll
    for (int t = 0; t < 2; t++) {
        int idx = tid + t * 256, r = idx >> 5, c4 = idx & 31;
        ((float4*)&embs[r][c4 * 4])[0] = e_pf[t];
    }
    #pragma unroll
    for (int t = 0; t < 8; t++) {
        int idx = tid + t * 256, kk = idx >> 4, q = idx & 15;
        ((float4*)&w1s[kk][0])[q] = w_pf[t];
    }
    __syncthreads();

    // ---- issue tile-1 global loads (consumed after tile-0 compute) ----
    #pragma unroll
    for (int t = 0; t < 2; t++) {
        int idx = tid + t * 256, r = idx >> 5, c4 = idx & 31;
        e_pf[t] = ((const float4*)(emb + (size_t)(n0 + r) * DIN + 128))[c4];
    }
    #pragma unroll
    for (int t = 0; t < 8; t++) {
        int idx = tid + t * 256, kk = idx >> 4, q = idx & 15;
        w_pf[t] = ((const float4*)(W1 + (size_t)(koff + 128 + kk) * H))[q];
    }

    // ---- compute tile 0 ----
    #pragma unroll 16
    for (int kk = 0; kk < 128; kk++) {
        float2 w = w1s[kk][hp];
        float e0 = embs[ng][kk];
        float e1 = embs[ng + 8][kk];
        acc00 += e0 * w.x;  acc01 += e0 * w.y;
        acc10 += e1 * w.x;  acc11 += e1 * w.y;
    }
    __syncthreads();

    // ---- store tile 1 to smem, compute ----
    #pragma unroll
    for (int t = 0; t < 2; t++) {
        int idx = tid + t * 256, r = idx >> 5, c4 = idx & 31;
        ((float4*)&embs[r][c4 * 4])[0] = e_pf[t];
    }
    #pragma unroll
    for (int t = 0; t < 8; t++) {
        int idx = tid + t * 256, kk = idx >> 4, q = idx & 15;
        ((float4*)&w1s[kk][0])[q] = w_pf[t];
    }
    __syncthreads();

    #pragma unroll 16
    for (int kk = 0; kk < 128; kk++) {
        float2 w = w1s[kk][hp];
        float e0 = embs[ng][kk];
        float e1 = embs[ng + 8][kk];
        acc00 += e0 * w.x;  acc01 += e0 * w.y;
        acc10 += e1 * w.x;  acc11 += e1 * w.y;
    }

    float2* outh = (float2*)(which ? g_abh : g_agh);
    outh[(size_t)(n0 + ng) * HP + hp]     = make_float2(acc00, acc01);
    outh[(size_t)(n0 + ng + 8) * HP + hp] = make_float2(acc10, acc11);
}

// ---------------------------------------------------------------------------
// Kernel 2: out[n,m] = sigmoid( sum_h relu(ag_h[n,h]+ab_h[m,h]) * W2[h] + b2 )
// 64x64 tile, 256 threads, 4x4 outputs/thread.
// Smem rows padded to 17 ulonglong2 (272B) -> LDS.128 loads of 2 h-pairs are
// bank-conflict-free (4-bank stride per phase lane). 16 loop iters of 2 hp.
// ---------------------------------------------------------------------------
__global__ void __launch_bounds__(256) outer_kernel(
    const float* __restrict__ W2, const float* __restrict__ b2,
    float* __restrict__ out)
{
    __shared__ ulonglong2 ags2[64 * 17];   // [n_local][hq], padded rows
    __shared__ ulonglong2 abss2[64 * 17];  // [m_local][hq]
    __shared__ ulonglong2 w2q[16];

    const int tid = threadIdx.x;
    const int n0 = blockIdx.y * 64;
    const int m0 = blockIdx.x * 64;

    // fill: 64 rows x 16 hq each
    #pragma unroll
    for (int t = 0; t < 4; t++) {
        int idx = tid + t * 256;            // 0..1023
        int r = idx >> 4, hq = idx & 15;
        ags2[r * 17 + hq]  = g_agh[(size_t)(n0 + r) * 16 + hq];
        abss2[r * 17 + hq] = g_abh[(size_t)(m0 + r) * 16 + hq];
    }
    if (tid < 16) w2q[tid] = ((const ulonglong2*)W2)[tid];
    __syncthreads();

    const int tx = tid & 15;   // m: m_local = tx + 16*j
    const int ty = tid >> 4;   // n: n_local = ty*4 + i

    const ulonglong2* aR0 = &ags2[(ty * 4) * 17];
    const ulonglong2* bR0 = &abss2[tx * 17];

    u64 acc[4][4];
    #pragma unroll
    for (int i = 0; i < 4; i++)
        #pragma unroll
        for (int j = 0; j < 4; j++) acc[i][j] = 0ull;

    #pragma unroll 2
    for (int hq = 0; hq < 16; hq++) {
        ulonglong2 wv = w2q[hq];
        ulonglong2 a[4], b[4];
        #pragma unroll
        for (int i = 0; i < 4; i++) a[i] = aR0[i * 17 + hq];
        #pragma unroll
        for (int j = 0; j < 4; j++) b[j] = bR0[j * 16 * 17 + hq];
        #pragma unroll
        for (int i = 0; i < 4; i++)
            #pragma unroll
            for (int j = 0; j < 4; j++) {
                acc[i][j] = f2fma(f2relu(f2add(a[i].x, b[j].x)), wv.x, acc[i][j]);
                acc[i][j] = f2fma(f2relu(f2add(a[i].y, b[j].y)), wv.y, acc[i][j]);
            }
    }

    const float b2v = *b2;
    #pragma unroll
    for (int i = 0; i < 4; i++) {
        int n = n0 + ty * 4 + i;
        #pragma unroll
        for (int j = 0; j < 4; j++) {
            float lo, hi;
            asm("mov.b64 {%0, %1}, %2;" : "=f"(lo), "=f"(hi) : "l"(acc[i][j]));
            float logit = lo + hi + b2v;
            out[(size_t)n * 2048 + m0 + tx + 16 * j] = 1.0f / (1.0f + __expf(-logit));
        }
    }
}

extern "C" void kernel_launch(void* const* d_in, const int* in_sizes, int n_in,
                              void* d_out, int out_size)
{
    const float* ag = (const float*)d_in[0];
    const float* ab = (const float*)d_in[1];
    const float* W1 = (const float*)d_in[2];
    const float* b1 = (const float*)d_in[3];
    const float* W2 = (const float*)d_in[4];
    const float* b2 = (const float*)d_in[5];
    float* out = (float*)d_out;

    hidden_kernel<<<256, 256>>>(ag, ab, W1, b1);

    dim3 grid(2048 / 64, 2048 / 64);
    outer_kernel<<<grid, 256>>>(W2, b2, out);
}